// round 17
// baseline (speedup 1.0000x reference)
#include <cuda_runtime.h>
#include <cuda_bf16.h>
#include <math.h>
#include <stdint.h>

#define N_NODES   50001
#define N_PAD     (N_NODES + 128)
#define N_NBRS    12
#define N_GRAPHS  1000
#define NEG_BIG   (-9000000000000000.0f)
#define HD        256

// ---------------------------------------------------------------------------
// Scratch: GEMM output stored as bf16 hi/lo pair. g_hh is the gather table.
// ---------------------------------------------------------------------------
__device__ unsigned short g_hh[(size_t)N_PAD * HD];
__device__ unsigned short g_hl[(size_t)N_PAD * HD];
__device__ unsigned short g_ah[(size_t)N_PAD * HD];
__device__ unsigned short g_al[(size_t)N_PAD * HD];

#define WCH 8192                          // 256*32
#define WT_TOTAL (20 * WCH)
__device__ unsigned short g_wbh[WT_TOTAL];
__device__ unsigned short g_wbl[WT_TOTAL];

// ---------------------------------------------------------------------------
// helpers
// ---------------------------------------------------------------------------
__device__ __forceinline__ unsigned short f2bf(float v) {
    return __bfloat16_as_ushort(__float2bfloat16_rn(v));
}
__device__ __forceinline__ float bf2f(unsigned short u) {
    return __bfloat162float(__ushort_as_bfloat16(u));
}
__device__ __forceinline__ uint32_t pack2(unsigned short a, unsigned short b) {
    return (uint32_t)a | ((uint32_t)b << 16);
}
__device__ __forceinline__ __nv_bfloat162 asbf2(uint32_t u) {
    __nv_bfloat162 r; memcpy(&r, &u, 4); return r;
}

__device__ __forceinline__ void mma_bf16(float* d, const uint32_t* a, const uint32_t* b) {
    asm volatile(
        "mma.sync.aligned.m16n8k16.row.col.f32.bf16.bf16.f32 "
        "{%0,%1,%2,%3}, {%4,%5,%6,%7}, {%8,%9}, {%0,%1,%2,%3};"
        : "+f"(d[0]), "+f"(d[1]), "+f"(d[2]), "+f"(d[3])
        : "r"(a[0]), "r"(a[1]), "r"(a[2]), "r"(a[3]), "r"(b[0]), "r"(b[1]));
}
#define LDMX4(r, addr) \
    asm volatile("ldmatrix.sync.aligned.m8n8.x4.shared.b16 {%0,%1,%2,%3}, [%4];" \
        : "=r"((r)[0]), "=r"((r)[1]), "=r"((r)[2]), "=r"((r)[3]) : "r"(addr))
#define CP16(dst, src) \
    asm volatile("cp.async.cg.shared.global [%0], [%1], 16;" :: "r"(dst), "l"(src) : "memory")
#define CPCOMMIT() asm volatile("cp.async.commit_group;" ::: "memory")
#define CPWAIT1()  asm volatile("cp.async.wait_group 1;" ::: "memory")
#define CPWAIT0()  asm volatile("cp.async.wait_group 0;" ::: "memory")

// ---------------------------------------------------------------------------
// Weight prep
// ---------------------------------------------------------------------------
__global__ void prep_w(const float* __restrict__ W0, const float* __restrict__ W1,
                       const float* __restrict__ W2,
                       unsigned short* __restrict__ bh, unsigned short* __restrict__ bl)
{
    int idx = blockIdx.x * blockDim.x + threadIdx.x;
    if (idx >= WT_TOTAL) return;
    const float* W; int K, base;
    if (idx < 4 * WCH)       { W = W0; K = 128; base = 0; }
    else if (idx < 12 * WCH) { W = W1; K = 256; base = 4 * WCH; }
    else                     { W = W2; K = 256; base = 12 * WCH; }
    int e = idx - base;
    int chunk = e >> 13;
    int rem   = e & 8191;
    int n  = rem >> 5;
    int kk = rem & 31;
    int h = n >> 5, o = n & 31;
    int k = chunk * 32 + kk;
    float v = W[((size_t)h * K + k) * 32 + o];
    unsigned short hi = f2bf(v);
    bh[idx] = hi;
    bl[idx] = f2bf(v - bf2f(hi));
}

// ---------------------------------------------------------------------------
// GEMM — R15 winner; FUSE_X variant converts fp32 x in the A-fill (layer 0),
// eliminating the separate split_x kernel. Layers 1/2 use the cp.async path.
// CTA 128x128, 8 warps (2m x 4n), warp 64x32, BK=32, 2-stage pipeline.
// ---------------------------------------------------------------------------
#define SROW 80
#define SARR 10240
#define SMEM_BYTES (8 * SARR)

template <bool FUSE_X>
__global__ __launch_bounds__(256, 2)
void gemm_mma(const float* __restrict__ X,
              const unsigned short* __restrict__ Ah, const unsigned short* __restrict__ Al,
              const unsigned short* __restrict__ wbh, const unsigned short* __restrict__ wbl,
              const float* __restrict__ bias,
              unsigned short* __restrict__ Hh, unsigned short* __restrict__ Hl,
              int K, int wbase)
{
    extern __shared__ char smem[];
    const uint32_t sbase = (uint32_t)__cvta_generic_to_shared(smem);

    const int tid  = threadIdx.x;
    const int wid  = tid >> 5;
    const int lane = tid & 31;
    const int g    = lane >> 2;
    const int t4   = lane & 3;
    const int wm   = wid & 1;
    const int wn   = wid >> 1;
    const int row0 = blockIdx.x * 128;
    const int col0 = blockIdx.y * 128;
    const int nch  = K >> 5;

    const int r_a  = tid >> 2, seg_a = tid & 3;

    const uint32_t aro = ((((lane >> 3) & 1) * 8 + (lane & 7)) * SROW) + ((lane >> 4) * 16);
    const uint32_t bro = ((((lane >> 4) & 1) * 8 + (lane & 7)) * SROW) + (((lane >> 3) & 1) * 16);

    auto fill = [&](int s, int c) {
        uint32_t stA = sbase + (s * 4) * SARR;
        uint32_t stB = sbase + (s * 4 + 2) * SARR;
        char* gA = smem + (size_t)(s * 4) * SARR;
        const unsigned short* srcB  = wbh + wbase + c * WCH + (col0 << 5);
        const unsigned short* srcBl = wbl + wbase + c * WCH + (col0 << 5);
#pragma unroll
        for (int i = 0; i < 2; i++) {
            int row = r_a + i * 64, seg = seg_a;
            if (FUSE_X) {
                int gr = row0 + row;
                float4 v1 = make_float4(0.f, 0.f, 0.f, 0.f);
                float4 v2 = make_float4(0.f, 0.f, 0.f, 0.f);
                if (gr < N_NODES) {
                    const float4* src = (const float4*)(X + (size_t)gr * K + c * 32 + seg * 8);
                    v1 = src[0];
                    v2 = src[1];
                }
                unsigned short h0 = f2bf(v1.x), h1 = f2bf(v1.y), h2 = f2bf(v1.z), h3 = f2bf(v1.w);
                unsigned short h4 = f2bf(v2.x), h5 = f2bf(v2.y), h6 = f2bf(v2.z), h7 = f2bf(v2.w);
                uint4 hw, lw;
                hw.x = pack2(h0, h1); hw.y = pack2(h2, h3);
                hw.z = pack2(h4, h5); hw.w = pack2(h6, h7);
                lw.x = pack2(f2bf(v1.x - bf2f(h0)), f2bf(v1.y - bf2f(h1)));
                lw.y = pack2(f2bf(v1.z - bf2f(h2)), f2bf(v1.w - bf2f(h3)));
                lw.z = pack2(f2bf(v2.x - bf2f(h4)), f2bf(v2.y - bf2f(h5)));
                lw.w = pack2(f2bf(v2.z - bf2f(h6)), f2bf(v2.w - bf2f(h7)));
                *(uint4*)(gA + row * SROW + seg * 16)        = hw;
                *(uint4*)(gA + SARR + row * SROW + seg * 16) = lw;
            } else {
                size_t aoff = (size_t)(row0 + row) * K + c * 32 + seg * 8;
                uint32_t d = stA + row * SROW + seg * 16;
                CP16(d,        Ah + aoff);
                CP16(d + SARR, Al + aoff);
            }
            size_t boff = (size_t)row * 32 + seg * 8;
            uint32_t db = stB + row * SROW + seg * 16;
            CP16(db,        srcB  + boff);
            CP16(db + SARR, srcBl + boff);
        }
    };

    float acc[4][4][4];
#pragma unroll
    for (int i = 0; i < 4; i++)
#pragma unroll
        for (int j = 0; j < 4; j++)
#pragma unroll
            for (int q = 0; q < 4; q++) acc[i][j][q] = 0.0f;

    fill(0, 0);
    CPCOMMIT();

    for (int c = 0; c < nch; c++) {
        int s = c & 1;
        if (c + 1 < nch) { fill(s ^ 1, c + 1); CPCOMMIT(); CPWAIT1(); }
        else             { CPWAIT0(); }
        __syncthreads();

        uint32_t stAh = sbase + (s * 4) * SARR + (wm * 64) * SROW + aro;
        uint32_t stAl = stAh + SARR;
        uint32_t stBh = sbase + (s * 4 + 2) * SARR + (wn * 32) * SROW + bro;
        uint32_t stBl = stBh + SARR;

#pragma unroll
        for (int k16 = 0; k16 < 2; k16++) {
            uint32_t ko = k16 * 32;
            uint32_t ah[4][4], al[4][4], bh4[2][4], bl4[2][4];
#pragma unroll
            for (int ma = 0; ma < 4; ma++) {
                LDMX4(ah[ma], stAh + ma * 16 * SROW + ko);
                LDMX4(al[ma], stAl + ma * 16 * SROW + ko);
            }
#pragma unroll
            for (int np = 0; np < 2; np++) {
                LDMX4(bh4[np], stBh + np * 16 * SROW + ko);
                LDMX4(bl4[np], stBl + np * 16 * SROW + ko);
            }
#pragma unroll
            for (int na = 0; na < 4; na++) {
                uint32_t bhf[2] = { bh4[na >> 1][(na & 1) * 2], bh4[na >> 1][(na & 1) * 2 + 1] };
                uint32_t blf[2] = { bl4[na >> 1][(na & 1) * 2], bl4[na >> 1][(na & 1) * 2 + 1] };
#pragma unroll
                for (int ma = 0; ma < 4; ma++) {
                    mma_bf16(acc[ma][na], ah[ma], bhf);
                    mma_bf16(acc[ma][na], ah[ma], blf);
                    mma_bf16(acc[ma][na], al[ma], bhf);
                }
            }
        }
        __syncthreads();
    }

#pragma unroll
    for (int ma = 0; ma < 4; ma++) {
#pragma unroll
        for (int na = 0; na < 4; na++) {
            int cg = col0 + wn * 32 + na * 8 + t4 * 2;
            float bx = __ldg(&bias[cg]);
            float by = __ldg(&bias[cg + 1]);
            int r1 = row0 + wm * 64 + ma * 16 + g;
            int r2 = r1 + 8;
#pragma unroll
            for (int rr = 0; rr < 2; rr++) {
                int r = rr ? r2 : r1;
                if (r >= N_NODES) continue;
                float vx = acc[ma][na][rr * 2 + 0] + bx;
                float vy = acc[ma][na][rr * 2 + 1] + by;
                if (r == 0) { vx = NEG_BIG; vy = NEG_BIG; }
                unsigned short hx = f2bf(vx), hy = f2bf(vy);
                *(uint32_t*)(Hh + (size_t)r * HD + cg) = pack2(hx, hy);
                *(uint32_t*)(Hl + (size_t)r * HD + cg) =
                    pack2(f2bf(vx - bf2f(hx)), f2bf(vy - bf2f(hy)));
            }
        }
    }
}

// ---------------------------------------------------------------------------
// Attention (unchanged R15 winner): packed bf16x2 HFMA2 neighbor dots,
// own row hi+lo fp32, attn0 = 1/(1+sum exp(d-s0)).
// ---------------------------------------------------------------------------
__global__ __launch_bounds__(256)
void attn_kernel(const unsigned short* __restrict__ Hh, const unsigned short* __restrict__ Hl,
                 const int* __restrict__ a2a32,
                 unsigned short* __restrict__ outh, unsigned short* __restrict__ outl,
                 float* __restrict__ outf)
{
    const int gwarp = (blockIdx.x * blockDim.x + threadIdx.x) >> 5;
    if (gwarp >= N_NODES) return;
    const int node = gwarp;
    const int lane = threadIdx.x & 31;
    const int head = lane >> 2;
    const int part = lane & 3;

    const bool idx64 = ((a2a32[1] | a2a32[3] | a2a32[5] | a2a32[7]) == 0);

    const int off = head * 32 + part * 8;
    const uint32_t offb = (uint32_t)off * 2;

    uint32_t nofs[N_NBRS];
    if (!idx64) {
        const int4* p = (const int4*)(a2a32 + node * N_NBRS);
        int4 q0 = p[0], q1 = p[1], q2 = p[2];
        nofs[0] = ((uint32_t)q0.x << 9) + offb; nofs[1]  = ((uint32_t)q0.y << 9) + offb;
        nofs[2] = ((uint32_t)q0.z << 9) + offb; nofs[3]  = ((uint32_t)q0.w << 9) + offb;
        nofs[4] = ((uint32_t)q1.x << 9) + offb; nofs[5]  = ((uint32_t)q1.y << 9) + offb;
        nofs[6] = ((uint32_t)q1.z << 9) + offb; nofs[7]  = ((uint32_t)q1.w << 9) + offb;
        nofs[8] = ((uint32_t)q2.x << 9) + offb; nofs[9]  = ((uint32_t)q2.y << 9) + offb;
        nofs[10] = ((uint32_t)q2.z << 9) + offb; nofs[11] = ((uint32_t)q2.w << 9) + offb;
    } else {
#pragma unroll
        for (int k = 0; k < N_NBRS; k++)
            nofs[k] = ((uint32_t)a2a32[2 * (node * N_NBRS + k)] << 9) + offb;
    }
    const char* nb = (const char*)Hh;

    uint4 ph = *(const uint4*)(Hh + (size_t)node * HD + off);
    uint4 pl = *(const uint4*)(Hl + (size_t)node * HD + off);
    float hn[8];
    {
        uint32_t hw[4] = {ph.x, ph.y, ph.z, ph.w};
        uint32_t lw[4] = {pl.x, pl.y, pl.z, pl.w};
#pragma unroll
        for (int i = 0; i < 4; i++) {
            hn[2 * i]     = __uint_as_float(hw[i] << 16)         + __uint_as_float(lw[i] << 16);
            hn[2 * i + 1] = __uint_as_float(hw[i] & 0xffff0000u) + __uint_as_float(lw[i] & 0xffff0000u);
        }
    }
    const __nv_bfloat162 a0 = asbf2(ph.x), a1 = asbf2(ph.y),
                         a2 = asbf2(ph.z), a3 = asbf2(ph.w);

    float s = 0.f;
#pragma unroll
    for (int i = 0; i < 8; i++) s = fmaf(hn[i], hn[i], s);
    s += __shfl_xor_sync(0xffffffffu, s, 1);
    s += __shfl_xor_sync(0xffffffffu, s, 2);
    const float s0 = s;

    float d[N_NBRS];
#pragma unroll
    for (int half = 0; half < 2; half++) {
        uint4 p[6];
#pragma unroll
        for (int j = 0; j < 6; j++)
            p[j] = *(const uint4*)(nb + nofs[half * 6 + j]);
#pragma unroll
        for (int j = 0; j < 6; j++) {
            __nv_bfloat162 acc2 = __hmul2(a0, asbf2(p[j].x));
            acc2 = __hfma2(a1, asbf2(p[j].y), acc2);
            acc2 = __hfma2(a2, asbf2(p[j].z), acc2);
            acc2 = __hfma2(a3, asbf2(p[j].w), acc2);
            float2 f = __bfloat1622float2(acc2);
            float dd = f.x + f.y;
            dd += __shfl_xor_sync(0xffffffffu, dd, 1);
            dd += __shfl_xor_sync(0xffffffffu, dd, 2);
            d[half * 6 + j] = dd;
        }
    }

    float denom = 1.0f;
#pragma unroll
    for (int k = 0; k < N_NBRS; k++) denom += __expf(d[k] - s0);

    float attn0 = __fdividef(1.0f, denom);
    if (node == 0) attn0 = 0.0f;

    float v[8];
#pragma unroll
    for (int i = 0; i < 8; i++) v[i] = hn[i] * attn0;

    if (outf) {
        float* orow = outf + (size_t)node * HD + off;
        *(float4*)orow       = make_float4(v[0], v[1], v[2], v[3]);
        *(float4*)(orow + 4) = make_float4(v[4], v[5], v[6], v[7]);
    } else {
        unsigned short hh[8];
        uint4 hp, lp;
#pragma unroll
        for (int i = 0; i < 8; i++) hh[i] = f2bf(v[i]);
        hp.x = pack2(hh[0], hh[1]); hp.y = pack2(hh[2], hh[3]);
        hp.z = pack2(hh[4], hh[5]); hp.w = pack2(hh[6], hh[7]);
        lp.x = pack2(f2bf(v[0] - bf2f(hh[0])), f2bf(v[1] - bf2f(hh[1])));
        lp.y = pack2(f2bf(v[2] - bf2f(hh[2])), f2bf(v[3] - bf2f(hh[3])));
        lp.z = pack2(f2bf(v[4] - bf2f(hh[4])), f2bf(v[5] - bf2f(hh[5])));
        lp.w = pack2(f2bf(v[6] - bf2f(hh[6])), f2bf(v[7] - bf2f(hh[7])));
        *(uint4*)(outh + (size_t)node * HD + off) = hp;
        *(uint4*)(outl + (size_t)node * HD + off) = lp;
    }
}

// ---------------------------------------------------------------------------
// Readout
// ---------------------------------------------------------------------------
__global__ __launch_bounds__(256)
void readout_kernel(const float* __restrict__ node_repr,
                    const float* __restrict__ Wo1, const float* __restrict__ bo1,
                    const float* __restrict__ Wo2, const float* __restrict__ bo2,
                    float* __restrict__ graph_repr, float* __restrict__ y)
{
    __shared__ float g[HD];
    const int gi = blockIdx.x;
    const int c  = threadIdx.x;

    float ssum = 0.f;
    const float* base = node_repr + (size_t)(1 + gi * 50) * HD + c;
#pragma unroll 10
    for (int r = 0; r < 50; r++) ssum += base[(size_t)r * HD];
    g[c] = ssum;
    graph_repr[(size_t)gi * HD + c] = ssum;
    __syncthreads();

    if (c < 32) {
        float acc = bo1[c];
#pragma unroll 8
        for (int d = 0; d < HD; d++) acc = fmaf(g[d], Wo1[d * 32 + c], acc);
        acc = fmaxf(acc, 0.0f);
        float val = acc * Wo2[c];
#pragma unroll
        for (int o = 16; o > 0; o >>= 1)
            val += __shfl_xor_sync(0xffffffffu, val, o);
        if (c == 0) y[gi] = val + bo2[0];
    }
}

// ---------------------------------------------------------------------------
extern "C" void kernel_launch(void* const* d_in, const int* in_sizes, int n_in,
                              void* d_out, int out_size)
{
    const float* x   = (const float*)d_in[0];
    const int*   a2a = (const int*)d_in[1];
    const float* W0  = (const float*)d_in[3];
    const float* b0  = (const float*)d_in[4];
    const float* W1  = (const float*)d_in[5];
    const float* b1  = (const float*)d_in[6];
    const float* W2  = (const float*)d_in[7];
    const float* b2  = (const float*)d_in[8];
    const float* Wo1 = (const float*)d_in[9];
    const float* bo1 = (const float*)d_in[10];
    const float* Wo2 = (const float*)d_in[11];
    const float* bo2 = (const float*)d_in[12];

    float* out        = (float*)d_out;
    float* node_repr  = out;
    float* graph_repr = out + (size_t)N_NODES * HD;
    float* y          = graph_repr + (size_t)N_GRAPHS * HD;

    unsigned short *hh = nullptr, *hl = nullptr, *ah = nullptr, *al = nullptr;
    unsigned short *wbh = nullptr, *wbl = nullptr;
    cudaGetSymbolAddress((void**)&hh, g_hh);
    cudaGetSymbolAddress((void**)&hl, g_hl);
    cudaGetSymbolAddress((void**)&ah, g_ah);
    cudaGetSymbolAddress((void**)&al, g_al);
    cudaGetSymbolAddress((void**)&wbh, g_wbh);
    cudaGetSymbolAddress((void**)&wbl, g_wbl);

    cudaFuncSetAttribute(gemm_mma<true>,  cudaFuncAttributeMaxDynamicSharedMemorySize, SMEM_BYTES);
    cudaFuncSetAttribute(gemm_mma<false>, cudaFuncAttributeMaxDynamicSharedMemorySize, SMEM_BYTES);

    dim3 ggrid((N_NODES + 127) / 128, 2);
    const int attn_grid = (N_NODES + 7) / 8;

    prep_w<<<(WT_TOTAL + 255) / 256, 256>>>(W0, W1, W2, wbh, wbl);

    gemm_mma<true><<<ggrid, 256, SMEM_BYTES>>>(x, ah, al, wbh, wbl, b0, hh, hl, 128, 0);
    attn_kernel<<<attn_grid, 256>>>(hh, hl, a2a, ah, al, nullptr);
    gemm_mma<false><<<ggrid, 256, SMEM_BYTES>>>(nullptr, ah, al, wbh, wbl, b1, hh, hl, 256, 4 * WCH);
    attn_kernel<<<attn_grid, 256>>>(hh, hl, a2a, ah, al, nullptr);
    gemm_mma<false><<<ggrid, 256, SMEM_BYTES>>>(nullptr, ah, al, wbh, wbl, b2, hh, hl, 256, 12 * WCH);
    attn_kernel<<<attn_grid, 256>>>(hh, hl, a2a, nullptr, nullptr, node_repr);

    readout_kernel<<<N_GRAPHS, 256>>>(node_repr, Wo1, bo1, Wo2, bo2, graph_repr, y);
}